// round 2
// baseline (speedup 1.0000x reference)
#include <cuda_runtime.h>
#include <cuda_bf16.h>
#include <math.h>

// ----------------------------------------------------------------------------
// Problem constants
// ----------------------------------------------------------------------------
#define BB 16
#define SS 4096
#define DD 1024
#define KK 16
#define ITERS 3
#define SCALE 0.03125f            // D^-0.5 = 1/32
#define EPS_LN 1e-5f
#define EPS_ATTN 1e-8f

#define BK_ROWS ((size_t)BB * SS)         // 65536
#define SLOT_ELEMS ((size_t)BB * KK * DD) // 262144

// ----------------------------------------------------------------------------
// Scratch (device globals — no allocation allowed)
// ----------------------------------------------------------------------------
__device__ float g_kbuf[BK_ROWS * DD];        // 268 MB
__device__ float g_vbuf[BK_ROWS * DD];        // 268 MB
__device__ float g_attn[BK_ROWS * KK];        // [b][s][k]  4 MB
__device__ float g_partial[BB * 16 * KK];     // per-block softmax partial sums
__device__ float g_rowsum[BB * KK];
__device__ float g_slots[SLOT_ELEMS];
__device__ float g_lnbuf[SLOT_ELEMS];
__device__ float g_qbuf[SLOT_ELEMS];
__device__ float g_updbuf[SLOT_ELEMS];
__device__ float g_gibuf[(size_t)BB * KK * 3 * DD];
__device__ float g_ghbuf[(size_t)BB * KK * 3 * DD];
__device__ float g_h1buf[(size_t)BB * KK * 4 * DD];

// ----------------------------------------------------------------------------
// Generic NT GEMM:  C[M,N] = A[M,Kd] @ W[N,Kd]^T + bias  (opt. accumulate/GELU)
// BN=64, BK=16, 256 threads. BM/TM templated. All dims divide exactly.
// ----------------------------------------------------------------------------
template <int BM, int TM, int ACT, bool ACCUM>
__global__ __launch_bounds__(256) void gemm_nt(
    const float* __restrict__ A, const float* __restrict__ W,
    const float* __restrict__ bias, float* __restrict__ C,
    int N, int Kd)
{
    constexpr int BN = 64, BKs = 16;
    __shared__ __align__(16) float As[BKs][BM + 4];
    __shared__ __align__(16) float Bs[BKs][BN + 4];

    const int t  = threadIdx.x;
    const int m0 = blockIdx.y * BM;
    const int n0 = blockIdx.x * BN;
    const int tx = t & 15;   // n dir (4 cols each)
    const int ty = t >> 4;   // m dir (TM rows each)

    float acc[TM][4];
#pragma unroll
    for (int i = 0; i < TM; i++)
#pragma unroll
        for (int j = 0; j < 4; j++) acc[i][j] = 0.f;

    constexpr int AF4 = BM * BKs / 4;   // float4 count of A tile

    for (int k0 = 0; k0 < Kd; k0 += BKs) {
#pragma unroll
        for (int f = t; f < AF4; f += 256) {
            int row = f >> 2;          // BK/4 = 4 float4 per row
            int kg  = f & 3;
            float4 v = *reinterpret_cast<const float4*>(
                &A[(size_t)(m0 + row) * Kd + k0 + kg * 4]);
            As[kg * 4 + 0][row] = v.x; As[kg * 4 + 1][row] = v.y;
            As[kg * 4 + 2][row] = v.z; As[kg * 4 + 3][row] = v.w;
        }
        {
            int row = t >> 2;          // 64 rows * 4 f4 = 256 threads
            int kg  = t & 3;
            float4 v = *reinterpret_cast<const float4*>(
                &W[(size_t)(n0 + row) * Kd + k0 + kg * 4]);
            Bs[kg * 4 + 0][row] = v.x; Bs[kg * 4 + 1][row] = v.y;
            Bs[kg * 4 + 2][row] = v.z; Bs[kg * 4 + 3][row] = v.w;
        }
        __syncthreads();
#pragma unroll
        for (int kk = 0; kk < BKs; kk++) {
            float a[TM], b[4];
#pragma unroll
            for (int i = 0; i < TM; i += 4) {
                float4 av = *reinterpret_cast<const float4*>(&As[kk][ty * TM + i]);
                a[i] = av.x; a[i + 1] = av.y; a[i + 2] = av.z; a[i + 3] = av.w;
            }
            float4 bv = *reinterpret_cast<const float4*>(&Bs[kk][tx * 4]);
            b[0] = bv.x; b[1] = bv.y; b[2] = bv.z; b[3] = bv.w;
#pragma unroll
            for (int i = 0; i < TM; i++)
#pragma unroll
                for (int j = 0; j < 4; j++) acc[i][j] += a[i] * b[j];
        }
        __syncthreads();
    }

#pragma unroll
    for (int i = 0; i < TM; i++) {
        size_t m = (size_t)m0 + ty * TM + i;
        float* crow = &C[m * N + n0 + tx * 4];
#pragma unroll
        for (int j = 0; j < 4; j++) {
            float val = acc[i][j] + bias[n0 + tx * 4 + j];
            if (ACCUM) val += crow[j];
            if (ACT == 1) val = 0.5f * val * (1.f + erff(val * 0.70710678118654752f));
            crow[j] = val;
        }
    }
}

// ----------------------------------------------------------------------------
// slots init: broadcast slot_mu over batch
// ----------------------------------------------------------------------------
__global__ void init_slots_kernel(const float* __restrict__ mu, float* __restrict__ slots)
{
    int idx = blockIdx.x * 256 + threadIdx.x;     // < 262144
    slots[idx] = mu[idx & 16383];
}

// ----------------------------------------------------------------------------
// LayerNorm over rows of 1024 (256 rows), 256 threads/row
// ----------------------------------------------------------------------------
__global__ void ln_rows_kernel(const float* __restrict__ x, const float* __restrict__ g,
                               const float* __restrict__ b, float* __restrict__ y)
{
    int row = blockIdx.x;
    int t = threadIdx.x;
    const float4* xr = reinterpret_cast<const float4*>(x + (size_t)row * DD);
    float4 v = xr[t];
    float s1 = v.x + v.y + v.z + v.w;
    float s2 = v.x * v.x + v.y * v.y + v.z * v.z + v.w * v.w;
    int lane = t & 31, w = t >> 5;
#pragma unroll
    for (int off = 16; off > 0; off >>= 1) {
        s1 += __shfl_down_sync(0xffffffffu, s1, off);
        s2 += __shfl_down_sync(0xffffffffu, s2, off);
    }
    __shared__ float ss1[8], ss2[8];
    __shared__ float smu, srstd;
    if (lane == 0) { ss1[w] = s1; ss2[w] = s2; }
    __syncthreads();
    if (t == 0) {
        float S = 0.f, Q = 0.f;
#pragma unroll
        for (int i = 0; i < 8; i++) { S += ss1[i]; Q += ss2[i]; }
        float mu = S * (1.f / DD);
        float var = Q * (1.f / DD) - mu * mu;
        smu = mu; srstd = rsqrtf(var + EPS_LN);
    }
    __syncthreads();
    float mu = smu, r = srstd;
    float4 gv = reinterpret_cast<const float4*>(g)[t];
    float4 bv = reinterpret_cast<const float4*>(b)[t];
    float4 o;
    o.x = (v.x - mu) * r * gv.x + bv.x;
    o.y = (v.y - mu) * r * gv.y + bv.y;
    o.z = (v.z - mu) * r * gv.z + bv.z;
    o.w = (v.w - mu) * r * gv.w + bv.w;
    reinterpret_cast<float4*>(y + (size_t)row * DD)[t] = o;
}

// ----------------------------------------------------------------------------
// logits[b][s][k] = SCALE * dot(q[b][k], kbuf[b][s])   stored [b][s][16]
// grid (S/128, B), 256 threads; each thread: 8 s-rows x 1 slot
// ----------------------------------------------------------------------------
__global__ __launch_bounds__(256) void logits_kernel(
    const float* __restrict__ q, const float* __restrict__ kbuf,
    float* __restrict__ attn)
{
    int b = blockIdx.y;
    int s0 = blockIdx.x * 128;
    __shared__ __align__(16) float sK[128][36];
    __shared__ __align__(16) float sQ[16][36];
    int t = threadIdx.x;
    int kidx = t & 15;
    int sg   = (t >> 4) * 8;
    const float* kb = kbuf + ((size_t)b * SS + s0) * DD;
    const float* qb = q + (size_t)b * KK * DD;
    float acc[8];
#pragma unroll
    for (int i = 0; i < 8; i++) acc[i] = 0.f;

    for (int d0 = 0; d0 < DD; d0 += 32) {
#pragma unroll
        for (int f = t; f < 1024; f += 256) {
            int row = f >> 3, cg = f & 7;
            float4 v = *reinterpret_cast<const float4*>(&kb[(size_t)row * DD + d0 + cg * 4]);
            sK[row][cg * 4 + 0] = v.x; sK[row][cg * 4 + 1] = v.y;
            sK[row][cg * 4 + 2] = v.z; sK[row][cg * 4 + 3] = v.w;
        }
        if (t < 128) {
            int row = t >> 3, cg = t & 7;
            float4 v = *reinterpret_cast<const float4*>(&qb[(size_t)row * DD + d0 + cg * 4]);
            sQ[row][cg * 4 + 0] = v.x; sQ[row][cg * 4 + 1] = v.y;
            sQ[row][cg * 4 + 2] = v.z; sQ[row][cg * 4 + 3] = v.w;
        }
        __syncthreads();
#pragma unroll
        for (int d = 0; d < 32; d += 4) {
            float4 qv = *reinterpret_cast<const float4*>(&sQ[kidx][d]);
#pragma unroll
            for (int i = 0; i < 8; i++) {
                float4 kv = *reinterpret_cast<const float4*>(&sK[sg + i][d]);
                acc[i] += kv.x * qv.x + kv.y * qv.y + kv.z * qv.z + kv.w * qv.w;
            }
        }
        __syncthreads();
    }
#pragma unroll
    for (int i = 0; i < 8; i++)
        attn[((size_t)b * SS + s0 + sg + i) * KK + kidx] = acc[i] * SCALE;
}

// ----------------------------------------------------------------------------
// softmax over k (16 contiguous) per (b,s); also per-block partial row sums
// grid = B*16 blocks (each 256 s within one batch), 256 threads
// ----------------------------------------------------------------------------
__global__ void softmax_kernel(float* __restrict__ attn, float* __restrict__ partial)
{
    int blk = blockIdx.x;           // b*16 + chunk
    int b = blk >> 4;
    int s = (blk & 15) * 256 + threadIdx.x;
    float* a = attn + ((size_t)b * SS + s) * KK;
    float v[16];
    float4* a4 = reinterpret_cast<float4*>(a);
#pragma unroll
    for (int i = 0; i < 4; i++) {
        float4 x = a4[i];
        v[i * 4 + 0] = x.x; v[i * 4 + 1] = x.y; v[i * 4 + 2] = x.z; v[i * 4 + 3] = x.w;
    }
    float mx = v[0];
#pragma unroll
    for (int k = 1; k < 16; k++) mx = fmaxf(mx, v[k]);
    float sum = 0.f;
#pragma unroll
    for (int k = 0; k < 16; k++) { v[k] = expf(v[k] - mx); sum += v[k]; }
    float inv = 1.f / sum;
#pragma unroll
    for (int k = 0; k < 16; k++) v[k] *= inv;
#pragma unroll
    for (int i = 0; i < 4; i++) {
        float4 x;
        x.x = v[i * 4 + 0]; x.y = v[i * 4 + 1]; x.z = v[i * 4 + 2]; x.w = v[i * 4 + 3];
        a4[i] = x;
    }
    // deterministic per-block reduction of sums over s for each k
    int lane = threadIdx.x & 31, w = threadIdx.x >> 5;
    __shared__ float ws[8][16];
#pragma unroll
    for (int k = 0; k < 16; k++) {
        float x = v[k];
#pragma unroll
        for (int off = 16; off > 0; off >>= 1) x += __shfl_down_sync(0xffffffffu, x, off);
        if (lane == 0) ws[w][k] = x;
    }
    __syncthreads();
    if (threadIdx.x < 16) {
        float sacc = 0.f;
#pragma unroll
        for (int ww = 0; ww < 8; ww++) sacc += ws[ww][threadIdx.x];
        partial[(size_t)blk * KK + threadIdx.x] = sacc;
    }
}

__global__ void rowsum_kernel(const float* __restrict__ partial, float* __restrict__ rowsum)
{
    int t = threadIdx.x;            // 256 = b*16 + k
    int b = t >> 4, k = t & 15;
    float s = 0.f;
#pragma unroll
    for (int c = 0; c < 16; c++) s += partial[((size_t)(b * 16 + c)) * KK + k];
    rowsum[t] = s;
}

// ----------------------------------------------------------------------------
// updates[b][k][d] = (1/(rowsum+eps)) * sum_s attn[b][s][k] * v[b][s][d]
// grid (D/128, B); each thread: 8 k x 1 d
// ----------------------------------------------------------------------------
__global__ __launch_bounds__(256) void updates_kernel(
    const float* __restrict__ attn, const float* __restrict__ rowsum,
    const float* __restrict__ vbuf, float* __restrict__ upd)
{
    int b = blockIdx.y;
    int d0 = blockIdx.x * 128;
    __shared__ float sV[32][128];
    __shared__ __align__(16) float sA[32][20];
    __shared__ float rs[16];
    int t = threadIdx.x;
    if (t < 16) rs[t] = 1.f / (rowsum[b * 16 + t] + EPS_ATTN);
    int dl = t & 127;
    int kg = (t >> 7) * 8;
    float acc[8];
#pragma unroll
    for (int j = 0; j < 8; j++) acc[j] = 0.f;
    const float* vb = vbuf + (size_t)b * SS * DD;
    const float* ab = attn + (size_t)b * SS * KK;
    __syncthreads();

    for (int s0 = 0; s0 < SS; s0 += 32) {
#pragma unroll
        for (int f = t; f < 1024; f += 256) {
            int row = f >> 5, cg = f & 31;
            float4 v = *reinterpret_cast<const float4*>(&vb[(size_t)(s0 + row) * DD + d0 + cg * 4]);
            sV[row][cg * 4 + 0] = v.x; sV[row][cg * 4 + 1] = v.y;
            sV[row][cg * 4 + 2] = v.z; sV[row][cg * 4 + 3] = v.w;
        }
#pragma unroll
        for (int f = t; f < 512; f += 256) {
            int srow = f >> 4, k = f & 15;
            sA[srow][k] = ab[(size_t)(s0 + srow) * KK + k];
        }
        __syncthreads();
#pragma unroll 8
        for (int s = 0; s < 32; s++) {
            float va = sV[s][dl];
            float4 a0 = *reinterpret_cast<const float4*>(&sA[s][kg]);
            float4 a1 = *reinterpret_cast<const float4*>(&sA[s][kg + 4]);
            acc[0] += a0.x * va; acc[1] += a0.y * va; acc[2] += a0.z * va; acc[3] += a0.w * va;
            acc[4] += a1.x * va; acc[5] += a1.y * va; acc[6] += a1.z * va; acc[7] += a1.w * va;
        }
        __syncthreads();
    }
#pragma unroll
    for (int j = 0; j < 8; j++)
        upd[((size_t)b * KK + kg + j) * DD + d0 + dl] = acc[j] * rs[kg + j];
}

// ----------------------------------------------------------------------------
// GRU combine (elementwise), slots updated in place
// ----------------------------------------------------------------------------
__global__ void gru_kernel(const float* __restrict__ gi, const float* __restrict__ gh,
                           float* __restrict__ slots)
{
    int idx = blockIdx.x * 256 + threadIdx.x;   // < 262144
    int m = idx >> 10, d = idx & 1023;
    size_t base = (size_t)m * 3072 + d;
    float ir = gi[base], iz = gi[base + 1024], in_ = gi[base + 2048];
    float hr = gh[base], hz = gh[base + 1024], hn  = gh[base + 2048];
    float r = 1.f / (1.f + expf(-(ir + hr)));
    float z = 1.f / (1.f + expf(-(iz + hz)));
    float n = tanhf(in_ + r * hn);
    float sp = slots[idx];
    slots[idx] = (1.f - z) * n + z * sp;
}

// ----------------------------------------------------------------------------
// output writers
// ----------------------------------------------------------------------------
__global__ void copy_kernel(const float* __restrict__ src, float* __restrict__ dst)
{
    int idx = blockIdx.x * 256 + threadIdx.x;
    dst[idx] = src[idx];
}

__global__ void attn_out_kernel(const float* __restrict__ attn, float* __restrict__ out)
{
    int idx = blockIdx.x * 256 + threadIdx.x;   // < B*K*S
    int s = idx & 4095;
    int k = (idx >> 12) & 15;
    int b = idx >> 16;
    out[idx] = attn[((size_t)b * SS + s) * KK + k];
}

// ----------------------------------------------------------------------------
// host
// ----------------------------------------------------------------------------
extern "C" void kernel_launch(void* const* d_in, const int* in_sizes, int n_in,
                              void* d_out, int out_size)
{
    const float* tokens  = (const float*)d_in[0];
    const float* slot_mu = (const float*)d_in[1];
    const float* Wq   = (const float*)d_in[2];
    const float* bq   = (const float*)d_in[3];
    const float* Wk   = (const float*)d_in[4];
    const float* bk   = (const float*)d_in[5];
    const float* Wv   = (const float*)d_in[6];
    const float* bv   = (const float*)d_in[7];
    const float* W_ih = (const float*)d_in[8];
    const float* b_ih = (const float*)d_in[9];
    const float* W_hh = (const float*)d_in[10];
    const float* b_hh = (const float*)d_in[11];
    const float* W1   = (const float*)d_in[12];
    const float* b1   = (const float*)d_in[13];
    const float* W2   = (const float*)d_in[14];
    const float* b2   = (const float*)d_in[15];
    const float* gam_slots = (const float*)d_in[16];
    const float* bet_slots = (const float*)d_in[17];
    const float* gam_mlp   = (const float*)d_in[18];
    const float* bet_mlp   = (const float*)d_in[19];
    float* out = (float*)d_out;

    float *kbuf, *vbuf, *attn, *partial, *rowsum, *slots, *lnbuf, *qbuf, *updbuf, *gibuf, *ghbuf, *h1buf;
    cudaGetSymbolAddress((void**)&kbuf,   g_kbuf);
    cudaGetSymbolAddress((void**)&vbuf,   g_vbuf);
    cudaGetSymbolAddress((void**)&attn,   g_attn);
    cudaGetSymbolAddress((void**)&partial,g_partial);
    cudaGetSymbolAddress((void**)&rowsum, g_rowsum);
    cudaGetSymbolAddress((void**)&slots,  g_slots);
    cudaGetSymbolAddress((void**)&lnbuf,  g_lnbuf);
    cudaGetSymbolAddress((void**)&qbuf,   g_qbuf);
    cudaGetSymbolAddress((void**)&updbuf, g_updbuf);
    cudaGetSymbolAddress((void**)&gibuf,  g_gibuf);
    cudaGetSymbolAddress((void**)&ghbuf,  g_ghbuf);
    cudaGetSymbolAddress((void**)&h1buf,  g_h1buf);

    // K/V projections: M=65536, N=1024, Kd=1024
    dim3 gkv(DD / 64, (unsigned)(BK_ROWS / 128));
    gemm_nt<128, 8, 0, false><<<gkv, 256>>>(tokens, Wk, bk, kbuf, DD, DD);
    gemm_nt<128, 8, 0, false><<<gkv, 256>>>(tokens, Wv, bv, vbuf, DD, DD);

    init_slots_kernel<<<SLOT_ELEMS / 256, 256>>>(slot_mu, slots);

    for (int it = 0; it < ITERS; it++) {
        // q = LN(slots) @ Wq^T + bq
        ln_rows_kernel<<<BB * KK, 256>>>(slots, gam_slots, bet_slots, lnbuf);
        gemm_nt<64, 4, 0, false><<<dim3(DD / 64, BB * KK / 64), 256>>>(lnbuf, Wq, bq, qbuf, DD, DD);

        // logits -> softmax over slots -> row sums
        logits_kernel<<<dim3(SS / 128, BB), 256>>>(qbuf, kbuf, attn);
        softmax_kernel<<<BB * 16, 256>>>(attn, partial);
        rowsum_kernel<<<1, 256>>>(partial, rowsum);

        // updates = attn_n @ v
        updates_kernel<<<dim3(DD / 128, BB), 256>>>(attn, rowsum, vbuf, updbuf);

        // GRU
        gemm_nt<64, 4, 0, false><<<dim3(3 * DD / 64, BB * KK / 64), 256>>>(updbuf, W_ih, b_ih, gibuf, 3 * DD, DD);
        gemm_nt<64, 4, 0, false><<<dim3(3 * DD / 64, BB * KK / 64), 256>>>(slots, W_hh, b_hh, ghbuf, 3 * DD, DD);
        gru_kernel<<<SLOT_ELEMS / 256, 256>>>(gibuf, ghbuf, slots);

        // MLP residual
        ln_rows_kernel<<<BB * KK, 256>>>(slots, gam_mlp, bet_mlp, lnbuf);
        gemm_nt<64, 4, 1, false><<<dim3(4 * DD / 64, BB * KK / 64), 256>>>(lnbuf, W1, b1, h1buf, 4 * DD, DD);
        gemm_nt<64, 4, 0, true><<<dim3(DD / 64, BB * KK / 64), 256>>>(h1buf, W2, b2, slots, DD, 4 * DD);
    }

    // outputs: slots then attn (transposed back to [b][k][s])
    copy_kernel<<<SLOT_ELEMS / 256, 256>>>(slots, out);
    attn_out_kernel<<<(BB * KK * SS) / 256, 256>>>(attn, out + SLOT_ELEMS);
}

// round 3
// speedup vs baseline: 2.0440x; 2.0440x over previous
#include <cuda_runtime.h>
#include <cuda_bf16.h>
#include <math.h>

// ----------------------------------------------------------------------------
// Problem constants
// ----------------------------------------------------------------------------
#define BB 16
#define SS 4096
#define DD 1024
#define KK 16
#define ITERS 3
#define SCALE 0.03125f            // D^-0.5 = 1/32
#define EPS_LN 1e-5f
#define EPS_ATTN 1e-8f

#define BK_ROWS ((size_t)BB * SS)         // 65536
#define SLOT_ELEMS ((size_t)BB * KK * DD) // 262144

// ----------------------------------------------------------------------------
// Scratch (device globals — no allocation allowed)
// ----------------------------------------------------------------------------
__device__ float g_kbuf[BK_ROWS * DD];        // 268 MB
__device__ float g_vbuf[BK_ROWS * DD];        // 268 MB
__device__ float g_attn[BK_ROWS * KK];        // [b][s][k]  4 MB
__device__ float g_partial[BB * 16 * KK];     // per-block softmax partial sums
__device__ float g_rowsum[BB * KK];
__device__ float g_slots[SLOT_ELEMS];
__device__ float g_lnbuf[SLOT_ELEMS];
__device__ float g_qbuf[SLOT_ELEMS];
__device__ float g_updbuf[SLOT_ELEMS];
__device__ float g_gibuf[(size_t)BB * KK * 3 * DD];
__device__ float g_ghbuf[(size_t)BB * KK * 3 * DD];
__device__ float g_h1buf[(size_t)BB * KK * 4 * DD];

// ----------------------------------------------------------------------------
// tf32 helpers
// ----------------------------------------------------------------------------
__device__ __forceinline__ unsigned f2tf(float x)
{
    unsigned u;
    asm("cvt.rna.tf32.f32 %0, %1;" : "=r"(u) : "f"(x));
    return u;
}

#define CP_ASYNC16(dst_u32, src_ptr) \
    asm volatile("cp.async.cg.shared.global [%0], [%1], 16;\n" :: "r"(dst_u32), "l"(src_ptr))
#define CP_COMMIT() asm volatile("cp.async.commit_group;\n")
#define CP_WAIT1()  asm volatile("cp.async.wait_group 1;\n")
#define CP_WAIT0()  asm volatile("cp.async.wait_group 0;\n")

// ----------------------------------------------------------------------------
// tf32 tensor-core NT GEMM:
//   C[M,N] = A[M,Kd] @ W[N,Kd]^T + bias   (opt accumulate-into-C, opt GELU)
// 256 threads = 8 warps laid out (BM/WM) x (BN/WN) = 2 x 4.
// mma.sync m16n8k8 tf32, double-buffered cp.async staging, BK=16.
// Requires: M % BM == 0, N % BN == 0, Kd % 16 == 0 (all true here).
// ----------------------------------------------------------------------------
template <int BM, int BN, int WM, int WN, int ACT, bool ACCUM>
__global__ __launch_bounds__(256) void gemm_tf32(
    const float* __restrict__ A, const float* __restrict__ W,
    const float* __restrict__ bias, float* __restrict__ C,
    int N, int Kd)
{
    constexpr int BK = 16, PAD = 20;            // PAD: bank-conflict-free, 16B-aligned rows
    constexpr int MT = WM / 16, NT = WN / 8;
    constexpr int WARPS_N = BN / WN;

    __shared__ __align__(16) float As[2][BM][PAD];
    __shared__ __align__(16) float Bs[2][BN][PAD];

    const int t = threadIdx.x;
    const int warp = t >> 5, lane = t & 31;
    const int wm = warp / WARPS_N, wn = warp % WARPS_N;
    const int m0 = blockIdx.y * BM, n0 = blockIdx.x * BN;
    const int r = lane >> 2, c = lane & 3;

    float acc[MT][NT][4];
#pragma unroll
    for (int i = 0; i < MT; i++)
#pragma unroll
        for (int j = 0; j < NT; j++)
#pragma unroll
            for (int q = 0; q < 4; q++) acc[i][j][q] = 0.f;

    const int ntiles = Kd / BK;

    // prologue: stage tile 0
    {
#pragma unroll
        for (int f = t; f < BM * 4; f += 256) {
            int row = f >> 2, cg = f & 3;
            unsigned dst = (unsigned)__cvta_generic_to_shared(&As[0][row][cg * 4]);
            CP_ASYNC16(dst, &A[(size_t)(m0 + row) * Kd + cg * 4]);
        }
#pragma unroll
        for (int f = t; f < BN * 4; f += 256) {
            int row = f >> 2, cg = f & 3;
            unsigned dst = (unsigned)__cvta_generic_to_shared(&Bs[0][row][cg * 4]);
            CP_ASYNC16(dst, &W[(size_t)(n0 + row) * Kd + cg * 4]);
        }
        CP_COMMIT();
    }

    for (int kt = 0; kt < ntiles; kt++) {
        if (kt + 1 < ntiles) {
            const int s = (kt + 1) & 1;
            const int k0 = (kt + 1) * BK;
#pragma unroll
            for (int f = t; f < BM * 4; f += 256) {
                int row = f >> 2, cg = f & 3;
                unsigned dst = (unsigned)__cvta_generic_to_shared(&As[s][row][cg * 4]);
                CP_ASYNC16(dst, &A[(size_t)(m0 + row) * Kd + k0 + cg * 4]);
            }
#pragma unroll
            for (int f = t; f < BN * 4; f += 256) {
                int row = f >> 2, cg = f & 3;
                unsigned dst = (unsigned)__cvta_generic_to_shared(&Bs[s][row][cg * 4]);
                CP_ASYNC16(dst, &W[(size_t)(n0 + row) * Kd + k0 + cg * 4]);
            }
            CP_COMMIT();
            CP_WAIT1();
        } else {
            CP_WAIT0();
        }
        __syncthreads();

        const int buf = kt & 1;
#pragma unroll
        for (int ks = 0; ks < BK; ks += 8) {
            unsigned af[MT][4], bf[NT][2];
#pragma unroll
            for (int i = 0; i < MT; i++) {
                const int mr = wm * WM + i * 16 + r;
                af[i][0] = f2tf(As[buf][mr][ks + c]);
                af[i][1] = f2tf(As[buf][mr + 8][ks + c]);
                af[i][2] = f2tf(As[buf][mr][ks + c + 4]);
                af[i][3] = f2tf(As[buf][mr + 8][ks + c + 4]);
            }
#pragma unroll
            for (int j = 0; j < NT; j++) {
                const int nr = wn * WN + j * 8 + r;
                bf[j][0] = f2tf(Bs[buf][nr][ks + c]);
                bf[j][1] = f2tf(Bs[buf][nr][ks + c + 4]);
            }
#pragma unroll
            for (int i = 0; i < MT; i++)
#pragma unroll
                for (int j = 0; j < NT; j++) {
                    asm volatile(
                        "mma.sync.aligned.m16n8k8.row.col.f32.tf32.tf32.f32 "
                        "{%0,%1,%2,%3}, {%4,%5,%6,%7}, {%8,%9}, {%0,%1,%2,%3};\n"
                        : "+f"(acc[i][j][0]), "+f"(acc[i][j][1]),
                          "+f"(acc[i][j][2]), "+f"(acc[i][j][3])
                        : "r"(af[i][0]), "r"(af[i][1]), "r"(af[i][2]), "r"(af[i][3]),
                          "r"(bf[j][0]), "r"(bf[j][1]));
                }
        }
        __syncthreads();
    }

    // epilogue
#pragma unroll
    for (int i = 0; i < MT; i++) {
        const int row = m0 + wm * WM + i * 16 + r;
#pragma unroll
        for (int j = 0; j < NT; j++) {
            const int col = n0 + wn * WN + j * 8 + 2 * c;
            const float b0v = bias[col], b1v = bias[col + 1];
            float v0 = acc[i][j][0] + b0v;
            float v1 = acc[i][j][1] + b1v;
            float v2 = acc[i][j][2] + b0v;
            float v3 = acc[i][j][3] + b1v;
            float* p0 = &C[(size_t)row * N + col];
            float* p1 = &C[(size_t)(row + 8) * N + col];
            if (ACCUM) {
                v0 += p0[0]; v1 += p0[1];
                v2 += p1[0]; v3 += p1[1];
            }
            if (ACT == 1) {
                v0 = 0.5f * v0 * (1.f + erff(v0 * 0.70710678118654752f));
                v1 = 0.5f * v1 * (1.f + erff(v1 * 0.70710678118654752f));
                v2 = 0.5f * v2 * (1.f + erff(v2 * 0.70710678118654752f));
                v3 = 0.5f * v3 * (1.f + erff(v3 * 0.70710678118654752f));
            }
            p0[0] = v0; p0[1] = v1;
            p1[0] = v2; p1[1] = v3;
        }
    }
}

// ----------------------------------------------------------------------------
// slots init: broadcast slot_mu over batch
// ----------------------------------------------------------------------------
__global__ void init_slots_kernel(const float* __restrict__ mu, float* __restrict__ slots)
{
    int idx = blockIdx.x * 256 + threadIdx.x;     // < 262144
    slots[idx] = mu[idx & 16383];
}

// ----------------------------------------------------------------------------
// LayerNorm over rows of 1024 (256 rows), 256 threads/row
// ----------------------------------------------------------------------------
__global__ void ln_rows_kernel(const float* __restrict__ x, const float* __restrict__ g,
                               const float* __restrict__ b, float* __restrict__ y)
{
    int row = blockIdx.x;
    int t = threadIdx.x;
    const float4* xr = reinterpret_cast<const float4*>(x + (size_t)row * DD);
    float4 v = xr[t];
    float s1 = v.x + v.y + v.z + v.w;
    float s2 = v.x * v.x + v.y * v.y + v.z * v.z + v.w * v.w;
    int lane = t & 31, w = t >> 5;
#pragma unroll
    for (int off = 16; off > 0; off >>= 1) {
        s1 += __shfl_down_sync(0xffffffffu, s1, off);
        s2 += __shfl_down_sync(0xffffffffu, s2, off);
    }
    __shared__ float ss1[8], ss2[8];
    __shared__ float smu, srstd;
    if (lane == 0) { ss1[w] = s1; ss2[w] = s2; }
    __syncthreads();
    if (t == 0) {
        float S = 0.f, Q = 0.f;
#pragma unroll
        for (int i = 0; i < 8; i++) { S += ss1[i]; Q += ss2[i]; }
        float mu = S * (1.f / DD);
        float var = Q * (1.f / DD) - mu * mu;
        smu = mu; srstd = rsqrtf(var + EPS_LN);
    }
    __syncthreads();
    float mu = smu, rr = srstd;
    float4 gv = reinterpret_cast<const float4*>(g)[t];
    float4 bv = reinterpret_cast<const float4*>(b)[t];
    float4 o;
    o.x = (v.x - mu) * rr * gv.x + bv.x;
    o.y = (v.y - mu) * rr * gv.y + bv.y;
    o.z = (v.z - mu) * rr * gv.z + bv.z;
    o.w = (v.w - mu) * rr * gv.w + bv.w;
    reinterpret_cast<float4*>(y + (size_t)row * DD)[t] = o;
}

// ----------------------------------------------------------------------------
// logits[b][s][k] = SCALE * dot(q[b][k], kbuf[b][s])   stored [b][s][16]
// grid (S/128, B), 256 threads; each thread: 8 s-rows x 1 slot
// ----------------------------------------------------------------------------
__global__ __launch_bounds__(256) void logits_kernel(
    const float* __restrict__ q, const float* __restrict__ kbuf,
    float* __restrict__ attn)
{
    int b = blockIdx.y;
    int s0 = blockIdx.x * 128;
    __shared__ __align__(16) float sK[128][36];
    __shared__ __align__(16) float sQ[16][36];
    int t = threadIdx.x;
    int kidx = t & 15;
    int sg   = (t >> 4) * 8;
    const float* kb = kbuf + ((size_t)b * SS + s0) * DD;
    const float* qb = q + (size_t)b * KK * DD;
    float acc[8];
#pragma unroll
    for (int i = 0; i < 8; i++) acc[i] = 0.f;

    for (int d0 = 0; d0 < DD; d0 += 32) {
#pragma unroll
        for (int f = t; f < 1024; f += 256) {
            int row = f >> 3, cg = f & 7;
            float4 v = *reinterpret_cast<const float4*>(&kb[(size_t)row * DD + d0 + cg * 4]);
            sK[row][cg * 4 + 0] = v.x; sK[row][cg * 4 + 1] = v.y;
            sK[row][cg * 4 + 2] = v.z; sK[row][cg * 4 + 3] = v.w;
        }
        if (t < 128) {
            int row = t >> 3, cg = t & 7;
            float4 v = *reinterpret_cast<const float4*>(&qb[(size_t)row * DD + d0 + cg * 4]);
            sQ[row][cg * 4 + 0] = v.x; sQ[row][cg * 4 + 1] = v.y;
            sQ[row][cg * 4 + 2] = v.z; sQ[row][cg * 4 + 3] = v.w;
        }
        __syncthreads();
#pragma unroll
        for (int d = 0; d < 32; d += 4) {
            float4 qv = *reinterpret_cast<const float4*>(&sQ[kidx][d]);
#pragma unroll
            for (int i = 0; i < 8; i++) {
                float4 kv = *reinterpret_cast<const float4*>(&sK[sg + i][d]);
                acc[i] += kv.x * qv.x + kv.y * qv.y + kv.z * qv.z + kv.w * qv.w;
            }
        }
        __syncthreads();
    }
#pragma unroll
    for (int i = 0; i < 8; i++)
        attn[((size_t)b * SS + s0 + sg + i) * KK + kidx] = acc[i] * SCALE;
}

// ----------------------------------------------------------------------------
// softmax over k (16 contiguous) per (b,s); also per-block partial row sums
// ----------------------------------------------------------------------------
__global__ void softmax_kernel(float* __restrict__ attn, float* __restrict__ partial)
{
    int blk = blockIdx.x;           // b*16 + chunk
    int b = blk >> 4;
    int s = (blk & 15) * 256 + threadIdx.x;
    float* a = attn + ((size_t)b * SS + s) * KK;
    float v[16];
    float4* a4 = reinterpret_cast<float4*>(a);
#pragma unroll
    for (int i = 0; i < 4; i++) {
        float4 x = a4[i];
        v[i * 4 + 0] = x.x; v[i * 4 + 1] = x.y; v[i * 4 + 2] = x.z; v[i * 4 + 3] = x.w;
    }
    float mx = v[0];
#pragma unroll
    for (int k = 1; k < 16; k++) mx = fmaxf(mx, v[k]);
    float sum = 0.f;
#pragma unroll
    for (int k = 0; k < 16; k++) { v[k] = expf(v[k] - mx); sum += v[k]; }
    float inv = 1.f / sum;
#pragma unroll
    for (int k = 0; k < 16; k++) v[k] *= inv;
#pragma unroll
    for (int i = 0; i < 4; i++) {
        float4 x;
        x.x = v[i * 4 + 0]; x.y = v[i * 4 + 1]; x.z = v[i * 4 + 2]; x.w = v[i * 4 + 3];
        a4[i] = x;
    }
    int lane = threadIdx.x & 31, w = threadIdx.x >> 5;
    __shared__ float ws[8][16];
#pragma unroll
    for (int k = 0; k < 16; k++) {
        float x = v[k];
#pragma unroll
        for (int off = 16; off > 0; off >>= 1) x += __shfl_down_sync(0xffffffffu, x, off);
        if (lane == 0) ws[w][k] = x;
    }
    __syncthreads();
    if (threadIdx.x < 16) {
        float sacc = 0.f;
#pragma unroll
        for (int ww = 0; ww < 8; ww++) sacc += ws[ww][threadIdx.x];
        partial[(size_t)blk * KK + threadIdx.x] = sacc;
    }
}

__global__ void rowsum_kernel(const float* __restrict__ partial, float* __restrict__ rowsum)
{
    int t = threadIdx.x;            // 256 = b*16 + k
    int b = t >> 4, k = t & 15;
    float s = 0.f;
#pragma unroll
    for (int c = 0; c < 16; c++) s += partial[((size_t)(b * 16 + c)) * KK + k];
    rowsum[t] = s;
}

// ----------------------------------------------------------------------------
// updates[b][k][d] = (1/(rowsum+eps)) * sum_s attn[b][s][k] * v[b][s][d]
// ----------------------------------------------------------------------------
__global__ __launch_bounds__(256) void updates_kernel(
    const float* __restrict__ attn, const float* __restrict__ rowsum,
    const float* __restrict__ vbuf, float* __restrict__ upd)
{
    int b = blockIdx.y;
    int d0 = blockIdx.x * 128;
    __shared__ float sV[32][128];
    __shared__ __align__(16) float sA[32][20];
    __shared__ float rs[16];
    int t = threadIdx.x;
    if (t < 16) rs[t] = 1.f / (rowsum[b * 16 + t] + EPS_ATTN);
    int dl = t & 127;
    int kg = (t >> 7) * 8;
    float acc[8];
#pragma unroll
    for (int j = 0; j < 8; j++) acc[j] = 0.f;
    const float* vb = vbuf + (size_t)b * SS * DD;
    const float* ab = attn + (size_t)b * SS * KK;
    __syncthreads();

    for (int s0 = 0; s0 < SS; s0 += 32) {
#pragma unroll
        for (int f = t; f < 1024; f += 256) {
            int row = f >> 5, cg = f & 31;
            float4 v = *reinterpret_cast<const float4*>(&vb[(size_t)(s0 + row) * DD + d0 + cg * 4]);
            sV[row][cg * 4 + 0] = v.x; sV[row][cg * 4 + 1] = v.y;
            sV[row][cg * 4 + 2] = v.z; sV[row][cg * 4 + 3] = v.w;
        }
#pragma unroll
        for (int f = t; f < 512; f += 256) {
            int srow = f >> 4, k = f & 15;
            sA[srow][k] = ab[(size_t)(s0 + srow) * KK + k];
        }
        __syncthreads();
#pragma unroll 8
        for (int s = 0; s < 32; s++) {
            float va = sV[s][dl];
            float4 a0 = *reinterpret_cast<const float4*>(&sA[s][kg]);
            float4 a1 = *reinterpret_cast<const float4*>(&sA[s][kg + 4]);
            acc[0] += a0.x * va; acc[1] += a0.y * va; acc[2] += a0.z * va; acc[3] += a0.w * va;
            acc[4] += a1.x * va; acc[5] += a1.y * va; acc[6] += a1.z * va; acc[7] += a1.w * va;
        }
        __syncthreads();
    }
#pragma unroll
    for (int j = 0; j < 8; j++)
        upd[((size_t)b * KK + kg + j) * DD + d0 + dl] = acc[j] * rs[kg + j];
}

// ----------------------------------------------------------------------------
// GRU combine (elementwise), slots updated in place
// ----------------------------------------------------------------------------
__global__ void gru_kernel(const float* __restrict__ gi, const float* __restrict__ gh,
                           float* __restrict__ slots)
{
    int idx = blockIdx.x * 256 + threadIdx.x;   // < 262144
    int m = idx >> 10, d = idx & 1023;
    size_t base = (size_t)m * 3072 + d;
    float ir = gi[base], iz = gi[base + 1024], in_ = gi[base + 2048];
    float hr = gh[base], hz = gh[base + 1024], hn  = gh[base + 2048];
    float r = 1.f / (1.f + expf(-(ir + hr)));
    float z = 1.f / (1.f + expf(-(iz + hz)));
    float n = tanhf(in_ + r * hn);
    float sp = slots[idx];
    slots[idx] = (1.f - z) * n + z * sp;
}

// ----------------------------------------------------------------------------
// output writers
// ----------------------------------------------------------------------------
__global__ void copy_kernel(const float* __restrict__ src, float* __restrict__ dst)
{
    int idx = blockIdx.x * 256 + threadIdx.x;
    dst[idx] = src[idx];
}

__global__ void attn_out_kernel(const float* __restrict__ attn, float* __restrict__ out)
{
    int idx = blockIdx.x * 256 + threadIdx.x;   // < B*K*S
    int s = idx & 4095;
    int k = (idx >> 12) & 15;
    int b = idx >> 16;
    out[idx] = attn[((size_t)b * SS + s) * KK + k];
}

// ----------------------------------------------------------------------------
// host
// ----------------------------------------------------------------------------
extern "C" void kernel_launch(void* const* d_in, const int* in_sizes, int n_in,
                              void* d_out, int out_size)
{
    const float* tokens  = (const float*)d_in[0];
    const float* slot_mu = (const float*)d_in[1];
    const float* Wq   = (const float*)d_in[2];
    const float* bq   = (const float*)d_in[3];
    const float* Wk   = (const float*)d_in[4];
    const float* bk   = (const float*)d_in[5];
    const float* Wv   = (const float*)d_in[6];
    const float* bv   = (const float*)d_in[7];
    const float* W_ih = (const float*)d_in[8];
    const float* b_ih = (const float*)d_in[9];
    const float* W_hh = (const float*)d_in[10];
    const float* b_hh = (const float*)d_in[11];
    const float* W1   = (const float*)d_in[12];
    const float* b1   = (const float*)d_in[13];
    const float* W2   = (const float*)d_in[14];
    const float* b2   = (const float*)d_in[15];
    const float* gam_slots = (const float*)d_in[16];
    const float* bet_slots = (const float*)d_in[17];
    const float* gam_mlp   = (const float*)d_in[18];
    const float* bet_mlp   = (const float*)d_in[19];
    float* out = (float*)d_out;

    float *kbuf, *vbuf, *attn, *partial, *rowsum, *slots, *lnbuf, *qbuf, *updbuf, *gibuf, *ghbuf, *h1buf;
    cudaGetSymbolAddress((void**)&kbuf,   g_kbuf);
    cudaGetSymbolAddress((void**)&vbuf,   g_vbuf);
    cudaGetSymbolAddress((void**)&attn,   g_attn);
    cudaGetSymbolAddress((void**)&partial,g_partial);
    cudaGetSymbolAddress((void**)&rowsum, g_rowsum);
    cudaGetSymbolAddress((void**)&slots,  g_slots);
    cudaGetSymbolAddress((void**)&lnbuf,  g_lnbuf);
    cudaGetSymbolAddress((void**)&qbuf,   g_qbuf);
    cudaGetSymbolAddress((void**)&updbuf, g_updbuf);
    cudaGetSymbolAddress((void**)&gibuf,  g_gibuf);
    cudaGetSymbolAddress((void**)&ghbuf,  g_ghbuf);
    cudaGetSymbolAddress((void**)&h1buf,  g_h1buf);

    // K/V projections: M=65536, N=1024, Kd=1024 (big tf32 config)
    dim3 gkv(DD / 128, (unsigned)(BK_ROWS / 128));
    gemm_tf32<128, 128, 64, 32, 0, false><<<gkv, 256>>>(tokens, Wk, bk, kbuf, DD, DD);
    gemm_tf32<128, 128, 64, 32, 0, false><<<gkv, 256>>>(tokens, Wv, bv, vbuf, DD, DD);

    init_slots_kernel<<<SLOT_ELEMS / 256, 256>>>(slot_mu, slots);

    for (int it = 0; it < ITERS; it++) {
        // q = LN(slots) @ Wq^T + bq
        ln_rows_kernel<<<BB * KK, 256>>>(slots, gam_slots, bet_slots, lnbuf);
        gemm_tf32<64, 64, 32, 16, 0, false><<<dim3(DD / 64, BB * KK / 64), 256>>>(lnbuf, Wq, bq, qbuf, DD, DD);

        // logits -> softmax over slots -> row sums
        logits_kernel<<<dim3(SS / 128, BB), 256>>>(qbuf, kbuf, attn);
        softmax_kernel<<<BB * 16, 256>>>(attn, partial);
        rowsum_kernel<<<1, 256>>>(partial, rowsum);

        // updates = attn_n @ v
        updates_kernel<<<dim3(DD / 128, BB), 256>>>(attn, rowsum, vbuf, updbuf);

        // GRU
        gemm_tf32<64, 64, 32, 16, 0, false><<<dim3(3 * DD / 64, BB * KK / 64), 256>>>(updbuf, W_ih, b_ih, gibuf, 3 * DD, DD);
        gemm_tf32<64, 64, 32, 16, 0, false><<<dim3(3 * DD / 64, BB * KK / 64), 256>>>(slots, W_hh, b_hh, ghbuf, 3 * DD, DD);
        gru_kernel<<<SLOT_ELEMS / 256, 256>>>(gibuf, ghbuf, slots);

        // MLP residual
        ln_rows_kernel<<<BB * KK, 256>>>(slots, gam_mlp, bet_mlp, lnbuf);
        gemm_tf32<64, 64, 32, 16, 1, false><<<dim3(4 * DD / 64, BB * KK / 64), 256>>>(lnbuf, W1, b1, h1buf, 4 * DD, DD);
        gemm_tf32<64, 64, 32, 16, 0, true><<<dim3(DD / 64, BB * KK / 64), 256>>>(h1buf, W2, b2, slots, DD, 4 * DD);
    }

    // outputs: slots then attn (transposed back to [b][k][s])
    copy_kernel<<<SLOT_ELEMS / 256, 256>>>(slots, out);
    attn_out_kernel<<<(BB * KK * SS) / 256, 256>>>(attn, out + SLOT_ELEMS);
}